// round 1
// baseline (speedup 1.0000x reference)
#include <cuda_runtime.h>
#include <math.h>

// Problem constants (fixed by the reference)
#define NN 8192
#define KK 16
#define GAMMA_MIN 0.9f
#define GAMMA_MAX 0.9995f

// Scratch: per-row compacted coefficient lists (allowed: __device__ globals)
__device__ int   g_nnz[NN];
__device__ int   g_kidx[NN * KK];
__device__ float g_cval[NN * KK];

// ---------------------------------------------------------------------------
// Pass 1: c[k][n] = gamma_k * v[k][n]; compact nonzeros per row n.
// Fully general (handles any nnz in [0,16]); for these inputs nnz == 1.
// ---------------------------------------------------------------------------
__global__ void build_coeffs_kernel(const float* __restrict__ eta,
                                    const float* __restrict__ v) {
    int n = blockIdx.x * blockDim.x + threadIdx.x;
    if (n >= NN) return;

    float gam[KK];
#pragma unroll
    for (int k = 0; k < KK; k++) {
        float e = eta[k];                      // broadcast, L1/const-cached
        float s = 1.0f / (1.0f + expf(-e));    // sigmoid
        gam[k] = GAMMA_MIN + (GAMMA_MAX - GAMMA_MIN) * s;
    }

    int cnt = 0;
#pragma unroll
    for (int k = 0; k < KK; k++) {
        float c = gam[k] * v[k * NN + n];      // coalesced across threads
        if (c != 0.0f) {
            g_kidx[n * KK + cnt] = k;
            g_cval[n * KK + cnt] = c;
            cnt++;
        }
    }
    for (int i = cnt; i < KK; i++) {           // pad so smem loads are safe
        g_kidx[n * KK + i] = 0;
        g_cval[n * KK + i] = 0.0f;
    }
    g_nnz[n] = cnt;
}

// ---------------------------------------------------------------------------
// Pass 2: W[n][m] = sum_i cval[n][i] * u[kidx[n][i]][m]
// Block tile: 32 rows x 1024 cols. 256 threads, one float4 column group each.
// u float4 per k is identical across the 32 rows -> L1 hit after first row.
// Output is write-once streaming -> __stcs.
// ---------------------------------------------------------------------------
#define ROWS_PER_BLOCK 32
#define THREADS 256
#define N4 (NN / 4)   // 2048 float4 per row

__global__ __launch_bounds__(THREADS)
void wslow_main_kernel(const float* __restrict__ u, float* __restrict__ out) {
    const int m4 = blockIdx.x * THREADS + threadIdx.x;   // float4 column index
    const int n0 = blockIdx.y * ROWS_PER_BLOCK;

    __shared__ int   s_nnz[ROWS_PER_BLOCK];
    __shared__ int   s_k[ROWS_PER_BLOCK][KK];
    __shared__ float s_c[ROWS_PER_BLOCK][KK];

    // Cooperative load of the 32 rows' coefficient lists (512 slots, 2 rounds)
    {
        int t = threadIdx.x;
        if (t < ROWS_PER_BLOCK) s_nnz[t] = g_nnz[n0 + t];
#pragma unroll
        for (int it = 0; it < 2; it++) {
            int slot = t + it * THREADS;                  // 0..511
            int r = slot >> 4;                            // row in tile
            int i = slot & 15;                            // slot in row
            s_k[r][i] = g_kidx[(n0 + r) * KK + i];
            s_c[r][i] = g_cval[(n0 + r) * KK + i];
        }
    }
    __syncthreads();

    const float4* __restrict__ u4 = reinterpret_cast<const float4*>(u);
    float4* __restrict__ o4 = reinterpret_cast<float4*>(out);

#pragma unroll 4
    for (int r = 0; r < ROWS_PER_BLOCK; r++) {
        float4 acc = make_float4(0.f, 0.f, 0.f, 0.f);
        const int nn = s_nnz[r];
        for (int i = 0; i < nn; i++) {
            const float  c  = s_c[r][i];
            const float4 uv = __ldg(&u4[s_k[r][i] * N4 + m4]);
            acc.x = fmaf(c, uv.x, acc.x);
            acc.y = fmaf(c, uv.y, acc.y);
            acc.z = fmaf(c, uv.z, acc.z);
            acc.w = fmaf(c, uv.w, acc.w);
        }
        // Always store (output buffer is poisoned) — streaming store
        __stcs(&o4[(n0 + r) * N4 + m4], acc);
    }
}

// ---------------------------------------------------------------------------
extern "C" void kernel_launch(void* const* d_in, const int* in_sizes, int n_in,
                              void* d_out, int out_size) {
    const float* eta = (const float*)d_in[0];   // [16]
    const float* v   = (const float*)d_in[1];   // [16, 8192]
    const float* u   = (const float*)d_in[2];   // [16, 8192]
    float* out = (float*)d_out;                 // [8192, 8192]

    build_coeffs_kernel<<<NN / THREADS, THREADS>>>(eta, v);

    dim3 grid(N4 / THREADS, NN / ROWS_PER_BLOCK);   // (8, 256)
    wslow_main_kernel<<<grid, THREADS>>>(u, out);
}

// round 2
// speedup vs baseline: 1.2206x; 1.2206x over previous
#include <cuda_runtime.h>
#include <math.h>

// Problem constants (fixed by the reference)
#define NN 8192
#define KK 16
#define GAMMA_MIN 0.9f
#define GAMMA_MAX 0.9995f

#define ROWS_PER_BLOCK 32
#define THREADS 256
#define N4 (NN / 4)   // 2048 float4 per row

// ---------------------------------------------------------------------------
// Fused single kernel.
//   Phase A (per block, tiny): gammas = sigmoid-scale of eta; then per-row
//     nonzero compaction of c[k] = gamma_k * v[k][n]  (general: nnz in [0,16]).
//   Phase B (the real work): W[n][m] = sum_i c_i * u[k_i][m], streamed out
//     as 128-bit stores. u reads are L1/L2-resident; a register cache of the
//     last-used u vector removes even the L1 hit on the common path where
//     consecutive rows reference the same k.
// ---------------------------------------------------------------------------
__global__ __launch_bounds__(THREADS)
void wslow_fused_kernel(const float* __restrict__ eta,
                        const float* __restrict__ v,
                        const float* __restrict__ u,
                        float* __restrict__ out) {
    const int m4 = blockIdx.x * THREADS + threadIdx.x;   // float4 column index
    const int n0 = blockIdx.y * ROWS_PER_BLOCK;          // first row of tile
    const int t  = threadIdx.x;

    __shared__ float s_gam[KK];
    __shared__ int   s_nnz[ROWS_PER_BLOCK];
    __shared__ int   s_k[ROWS_PER_BLOCK][KK];
    __shared__ float s_c[ROWS_PER_BLOCK][KK];

    // --- Phase A1: gammas (16 threads) ---
    if (t < KK) {
        float e = eta[t];
        float s = 1.0f / (1.0f + expf(-e));
        s_gam[t] = GAMMA_MIN + (GAMMA_MAX - GAMMA_MIN) * s;
    }
    __syncthreads();

    // --- Phase A2: per-row compaction (32 threads, one row each) ---
    if (t < ROWS_PER_BLOCK) {
        const int n = n0 + t;
        int cnt = 0;
#pragma unroll
        for (int k = 0; k < KK; k++) {
            float c = s_gam[k] * v[k * NN + n];
            if (c != 0.0f) {
                s_k[t][cnt] = k;
                s_c[t][cnt] = c;
                cnt++;
            }
        }
        s_nnz[t] = cnt;
    }
    __syncthreads();

    // --- Phase B: streamed outer-product accumulation ---
    const float4* __restrict__ u4 = reinterpret_cast<const float4*>(u);
    float4* __restrict__ o4 = reinterpret_cast<float4*>(out) + (size_t)n0 * N4 + m4;

    int    kprev = -1;
    float4 uv    = make_float4(0.f, 0.f, 0.f, 0.f);

#pragma unroll 8
    for (int r = 0; r < ROWS_PER_BLOCK; r++) {
        float4 acc = make_float4(0.f, 0.f, 0.f, 0.f);
        const int nn = s_nnz[r];
        for (int i = 0; i < nn; i++) {
            const int k = s_k[r][i];
            if (k != kprev) {                 // block-uniform branch
                uv = __ldg(&u4[k * N4 + m4]); // L1/L2-resident
                kprev = k;
            }
            const float c = s_c[r][i];
            acc.x = fmaf(c, uv.x, acc.x);
            acc.y = fmaf(c, uv.y, acc.y);
            acc.z = fmaf(c, uv.z, acc.z);
            acc.w = fmaf(c, uv.w, acc.w);
        }
        __stcs(o4, acc);                      // streaming 128-bit store
        o4 += N4;
    }
}

// ---------------------------------------------------------------------------
extern "C" void kernel_launch(void* const* d_in, const int* in_sizes, int n_in,
                              void* d_out, int out_size) {
    const float* eta = (const float*)d_in[0];   // [16]
    const float* v   = (const float*)d_in[1];   // [16, 8192]
    const float* u   = (const float*)d_in[2];   // [16, 8192]
    float* out = (float*)d_out;                 // [8192, 8192] fp32

    dim3 grid(N4 / THREADS, NN / ROWS_PER_BLOCK);   // (8, 256)
    wslow_fused_kernel<<<grid, THREADS>>>(eta, v, u, out);
}